// round 6
// baseline (speedup 1.0000x reference)
#include <cuda_runtime.h>
#include <cuda_fp16.h>
#include <cstdint>
#include <cstddef>

// ---------------- Problem dims ----------------
#define N_ROWS 8192
#define D_IN   4096
#define D_OUT  4096

// ---------------- GEMM tiling -----------------
#define TM 128
#define TN 256
#define TK 64
#define M_TILES 64      // 8192/128
#define N_TILES 16      // 4096/256
#define K_ITERS 64      // 4096/64 (single fp16 X image)
#define A_STAGE 16384   // TM*TK*2 bytes (fp16)
#define B_STAGE 32768   // TN*TK*2 bytes (fp16)
#define STAGE_BYTES 49152
#define NSTAGE 4
#define SMEM_DYN 197632 // 4*49152 + 1024 alignment slack

// Pre-swizzled, tile-ordered operand images (scratch via __device__ globals).
__device__ __align__(1024) uint8_t g_A[(size_t)M_TILES * K_ITERS * A_STAGE]; // 64 MB
__device__ __align__(1024) uint8_t g_B[(size_t)N_TILES * 64 * B_STAGE];      // 32 MB

// ---------------- helpers ----------------
static __device__ __forceinline__ uint32_t smem_u32(const void* p) {
    uint32_t a;
    asm("{ .reg .u64 t; cvta.to.shared.u64 t, %1; cvt.u32.u64 %0, t; }"
        : "=r"(a) : "l"(p));
    return a;
}

static __device__ __forceinline__ void cp16(uint32_t dst, const void* src) {
    asm volatile("cp.async.cg.shared.global [%0], [%1], 16;"
                 :: "r"(dst), "l"(src) : "memory");
}

static __device__ __forceinline__ void ldsm4(uint32_t (&r)[4], uint32_t addr) {
    asm volatile("ldmatrix.sync.aligned.m8n8.x4.shared.b16 {%0,%1,%2,%3}, [%4];"
                 : "=r"(r[0]), "=r"(r[1]), "=r"(r[2]), "=r"(r[3]) : "r"(addr));
}

static __device__ __forceinline__ void mma16816(float* d, const uint32_t* a,
                                                uint32_t b0, uint32_t b1) {
    asm volatile(
        "mma.sync.aligned.m16n8k16.row.col.f32.f16.f16.f32 "
        "{%0,%1,%2,%3}, {%4,%5,%6,%7}, {%8,%9}, {%0,%1,%2,%3};"
        : "+f"(d[0]), "+f"(d[1]), "+f"(d[2]), "+f"(d[3])
        : "r"(a[0]), "r"(a[1]), "r"(a[2]), "r"(a[3]), "r"(b0), "r"(b1));
}

// ============================================================================
// Prep X: fp32 X -> single fp16 image, pre-swizzled & tile-ordered.
// ============================================================================
__global__ void prep_x_kernel(const float* __restrict__ X) {
    int g  = blockIdx.x * 256 + threadIdx.x;   // 8192*512 chunks
    int n  = g >> 9;
    int k0 = (g & 511) << 3;
    const float4* xp = reinterpret_cast<const float4*>(X + (size_t)n * D_IN + k0);
    float4 a = xp[0], b = xp[1];
    union { __half h[8]; uint4 u; } hi;
    hi.h[0] = __float2half_rn(a.x); hi.h[1] = __float2half_rn(a.y);
    hi.h[2] = __float2half_rn(a.z); hi.h[3] = __float2half_rn(a.w);
    hi.h[4] = __float2half_rn(b.x); hi.h[5] = __float2half_rn(b.y);
    hi.h[6] = __float2half_rn(b.z); hi.h[7] = __float2half_rn(b.w);
    int mt = n >> 7, m = n & 127, ks = k0 >> 6, kk = k0 & 63;
    uint32_t off = (uint32_t)(m * 128 + kk * 2);
    uint32_t sw  = off ^ ((off >> 3) & 0x70u);
    *reinterpret_cast<uint4*>(g_A + (size_t)(mt * 64 + ks) * A_STAGE + sw) = hi.u;
}

// ============================================================================
// Prep W: W' = (W_nf4 * c1) * c_kbit2 + L1@L2, transposed to N-major [d][k],
// fp16, pre-swizzled & tile-ordered. Block tile: 64 k x 32 d.
// ============================================================================
__global__ void prep_w_kernel(const float* __restrict__ Wn, const float* __restrict__ c1p,
                              const float* __restrict__ ck, const float* __restrict__ L1,
                              const float* __restrict__ L2) {
    __shared__ float sL1[64 * 16];
    __shared__ float sL2[16 * 32];
    __shared__ __align__(16) __half sOut[32 * 64];
    const int t  = threadIdx.x;
    const int k0 = blockIdx.y * 64;
    const int d0 = blockIdx.x * 32;
    const float c1 = __ldg(c1p);

    for (int i = t; i < 1024; i += 256) sL1[i] = L1[(size_t)k0 * 16 + i];
    for (int i = t; i < 512;  i += 256) sL2[i] = L2[(size_t)(i >> 5) * D_OUT + d0 + (i & 31)];

    const int dd = t & 31;
    float wv[8];
#pragma unroll
    for (int i = 0; i < 8; i++) {
        int k = (t >> 5) + i * 8;
        size_t gi = (size_t)(k0 + k) * D_OUT + d0 + dd;
        wv[i] = (Wn[gi] * c1) * ck[gi];   // match reference mul order
    }
    __syncthreads();
#pragma unroll
    for (int i = 0; i < 8; i++) {
        int k = (t >> 5) + i * 8;
        float acc = wv[i];
#pragma unroll
        for (int r = 0; r < 16; r++) acc += sL1[k * 16 + r] * sL2[r * 32 + dd];
        sOut[dd * 64 + k] = __float2half_rn(acc);
    }
    __syncthreads();
    const int od = t >> 3, c = t & 7;
    uint4 v = *reinterpret_cast<uint4*>(&sOut[od * 64 + c * 8]);
    int ntile = blockIdx.x >> 3;
    int nloc  = ((blockIdx.x & 7) << 5) + od;
    uint32_t off = (uint32_t)(nloc * 128 + c * 16);
    uint32_t sw  = off ^ ((off >> 3) & 0x70u);
    *reinterpret_cast<uint4*>(g_B + (size_t)(ntile * 64 + blockIdx.y) * B_STAGE + sw) = v;
}

// ============================================================================
// GEMM: Y[8192,4096] = Xh @ W' via mma.sync.m16n8k16 (HMMA).
// CTA tile 128x256, warp grid 2(m)x4(n) of 64x64 warp tiles.
// 4-stage cp.async pipeline (wait<=2), one __syncthreads per K-iter,
// register double-buffered fragments across the 4 ks sub-steps.
// ============================================================================
static __device__ __forceinline__ void load_stage(uint32_t sA, uint32_t sB,
                                                  const uint8_t* gA, const uint8_t* gB,
                                                  int tid) {
#pragma unroll
    for (int i = 0; i < 4; i++) {
        uint32_t o = (uint32_t)(tid + i * 256) * 16u;
        cp16(sA + o, gA + o);
    }
#pragma unroll
    for (int i = 0; i < 8; i++) {
        uint32_t o = (uint32_t)(tid + i * 256) * 16u;
        cp16(sB + o, gB + o);
    }
}

static __device__ __forceinline__ void ld_frags(uint32_t (&a)[4][4], uint32_t (&b)[4][4],
                                                uint32_t sA, uint32_t sB, uint32_t kb,
                                                const uint32_t* aRowOff,
                                                const uint32_t* bRowOff) {
#pragma unroll
    for (int mi = 0; mi < 4; mi++) ldsm4(a[mi], sA + aRowOff[mi] + kb);
#pragma unroll
    for (int nj = 0; nj < 4; nj++) ldsm4(b[nj], sB + bRowOff[nj] + kb);
}

__global__ void __launch_bounds__(256, 1) qlora_gemm(float* __restrict__ Y) {
    extern __shared__ __align__(16) uint8_t smem[];
    const int tid  = threadIdx.x;
    const int wid  = tid >> 5;
    const int lane = tid & 31;
    const int nt = blockIdx.x;     // n-tile fastest -> W' stays L2-resident
    const int mt = blockIdx.y;

    const int wm = wid >> 2;       // 0..1
    const int wn = wid & 3;        // 0..3

    uint32_t base   = smem_u32(smem);
    uint32_t stage0 = (base + 1023u) & ~1023u;

    // SW128 within a 128B-row tile reduces to: addr = row*128 + (kb ^ ((row&7)*16)).
    const int lr = lane & 15;
    const int lk = (lane >> 4) * 16;
    const int xm = (lr & 7) * 16;
    uint32_t aRowOff[4], bRowOff[4];
#pragma unroll
    for (int mi = 0; mi < 4; mi++) aRowOff[mi] = (uint32_t)((wm * 64 + mi * 16 + lr) * 128);
#pragma unroll
    for (int nj = 0; nj < 4; nj++) bRowOff[nj] = (uint32_t)((wn * 64 + nj * 16 + lr) * 128);

    uint32_t kbs[4];
#pragma unroll
    for (int ks = 0; ks < 4; ks++) kbs[ks] = (uint32_t)((ks * 32 + lk) ^ xm);

    float acc[4][8][4];
#pragma unroll
    for (int mi = 0; mi < 4; mi++)
#pragma unroll
        for (int nj = 0; nj < 8; nj++)
#pragma unroll
            for (int c = 0; c < 4; c++) acc[mi][nj][c] = 0.0f;

    // prologue: fill NSTAGE-1 = 3 stages
#pragma unroll
    for (int s = 0; s < NSTAGE - 1; s++) {
        const uint8_t* gA = g_A + (size_t)(mt * 64 + s) * A_STAGE;
        const uint8_t* gB = g_B + (size_t)(nt * 64 + s) * B_STAGE;
        uint32_t sA = stage0 + s * STAGE_BYTES;
        load_stage(sA, sA + A_STAGE, gA, gB, tid);
        asm volatile("cp.async.commit_group;" ::: "memory");
    }

    uint32_t af[2][4][4], bf[2][4][4];
    int rbuf = 0, wbuf = NSTAGE - 1;
    for (int it = 0; it < K_ITERS; ++it) {
        uint32_t sA = stage0 + rbuf * STAGE_BYTES;
        uint32_t sB = sA + A_STAGE;
        asm volatile("cp.async.wait_group %0;" :: "n"(NSTAGE - 2) : "memory");
        __syncthreads();   // read-stage visible to all; wbuf (read last iter) free

        // kick off ks=0 fragment loads immediately (LDSM latency hides under
        // the cp.async refill issue burst below)
        ld_frags(af[0], bf[0], sA, sB, kbs[0], aRowOff, bRowOff);

        // refill: stage it+NSTAGE-1 into wbuf
        int nx = it + NSTAGE - 1;
        if (nx < K_ITERS) {
            const uint8_t* gA = g_A + (size_t)(mt * 64 + nx) * A_STAGE;
            const uint8_t* gB = g_B + (size_t)(nt * 64 + nx) * B_STAGE;
            uint32_t wA = stage0 + wbuf * STAGE_BYTES;
            load_stage(wA, wA + A_STAGE, gA, gB, tid);
        }
        asm volatile("cp.async.commit_group;" ::: "memory");

#pragma unroll
        for (int ks = 0; ks < 4; ks++) {
            const int cur = ks & 1, nxt = cur ^ 1;
            if (ks < 3)
                ld_frags(af[nxt], bf[nxt], sA, sB, kbs[ks + 1], aRowOff, bRowOff);
#pragma unroll
            for (int mi = 0; mi < 4; mi++)
#pragma unroll
                for (int nj = 0; nj < 4; nj++) {
                    mma16816(acc[mi][2 * nj],     af[cur][mi], bf[cur][nj][0], bf[cur][nj][2]);
                    mma16816(acc[mi][2 * nj + 1], af[cur][mi], bf[cur][nj][1], bf[cur][nj][3]);
                }
        }

        wbuf = rbuf;
        rbuf++; if (rbuf == NSTAGE) rbuf = 0;
    }

    // epilogue: direct fp32 stores
    float* yBase = Y + (size_t)(mt * 128 + wm * 64) * D_OUT + nt * 256 + wn * 64;
    const int qr = lane >> 2;
    const int qc = (lane & 3) * 2;
#pragma unroll
    for (int mi = 0; mi < 4; mi++) {
        float* y0 = yBase + (size_t)(mi * 16 + qr) * D_OUT + qc;
        float* y1 = y0 + (size_t)8 * D_OUT;
#pragma unroll
        for (int nj = 0; nj < 8; nj++) {
            *reinterpret_cast<float2*>(y0 + nj * 8) = make_float2(acc[mi][nj][0], acc[mi][nj][1]);
            *reinterpret_cast<float2*>(y1 + nj * 8) = make_float2(acc[mi][nj][2], acc[mi][nj][3]);
        }
    }
}

// ============================================================================
extern "C" void kernel_launch(void* const* d_in, const int* in_sizes, int n_in,
                              void* d_out, int out_size) {
    (void)in_sizes; (void)n_in; (void)out_size;
    const float* X  = (const float*)d_in[0];
    const float* Wn = (const float*)d_in[1];
    const float* c1 = (const float*)d_in[2];
    const float* ck = (const float*)d_in[3];
    const float* L1 = (const float*)d_in[4];
    const float* L2 = (const float*)d_in[5];
    float* Y = (float*)d_out;

    prep_x_kernel<<<16384, 256>>>(X);
    prep_w_kernel<<<dim3(128, 64), 256>>>(Wn, c1, ck, L1, L2);
    cudaFuncSetAttribute(qlora_gemm, cudaFuncAttributeMaxDynamicSharedMemorySize, SMEM_DYN);
    qlora_gemm<<<dim3(N_TILES, M_TILES), 256, SMEM_DYN>>>(Y);
}

// round 8
// speedup vs baseline: 1.0795x; 1.0795x over previous
#include <cuda_runtime.h>
#include <cuda_fp16.h>
#include <cstdint>
#include <cstddef>

// ---------------- Problem dims ----------------
#define N_ROWS 8192
#define D_IN   4096
#define D_OUT  4096

// ---------------- GEMM tiling -----------------
#define TM 128
#define TN 128
#define TK 64
#define M_TILES 64      // 8192/128
#define N_TILES 32      // 4096/128
#define K_ITERS 64      // 4096/64 (single fp16 X image)
#define A_STAGE 16384   // TM*TK*2 bytes (fp16)
#define B_STAGE 16384   // TN*TK*2 bytes (fp16)
#define STAGE_BYTES 32768
#define NSTAGE 3
#define SMEM_DYN 99328  // 3*32768 + 1024 alignment slack (x2 CTAs = 198KB/SM)

// Pre-swizzled, tile-ordered operand images (scratch via __device__ globals).
__device__ __align__(1024) uint8_t g_A[(size_t)M_TILES * K_ITERS * A_STAGE]; // 64 MB
__device__ __align__(1024) uint8_t g_B[(size_t)N_TILES * K_ITERS * B_STAGE]; // 32 MB

// ---------------- helpers ----------------
static __device__ __forceinline__ uint32_t smem_u32(const void* p) {
    uint32_t a;
    asm("{ .reg .u64 t; cvta.to.shared.u64 t, %1; cvt.u32.u64 %0, t; }"
        : "=r"(a) : "l"(p));
    return a;
}

static __device__ __forceinline__ void cp16(uint32_t dst, const void* src) {
    asm volatile("cp.async.cg.shared.global [%0], [%1], 16;"
                 :: "r"(dst), "l"(src) : "memory");
}

static __device__ __forceinline__ void ldsm4(uint32_t (&r)[4], uint32_t addr) {
    asm volatile("ldmatrix.sync.aligned.m8n8.x4.shared.b16 {%0,%1,%2,%3}, [%4];"
                 : "=r"(r[0]), "=r"(r[1]), "=r"(r[2]), "=r"(r[3]) : "r"(addr));
}

static __device__ __forceinline__ void mma16816(float* d, const uint32_t* a,
                                                uint32_t b0, uint32_t b1) {
    asm volatile(
        "mma.sync.aligned.m16n8k16.row.col.f32.f16.f16.f32 "
        "{%0,%1,%2,%3}, {%4,%5,%6,%7}, {%8,%9}, {%0,%1,%2,%3};"
        : "+f"(d[0]), "+f"(d[1]), "+f"(d[2]), "+f"(d[3])
        : "r"(a[0]), "r"(a[1]), "r"(a[2]), "r"(a[3]), "r"(b0), "r"(b1));
}

// ============================================================================
// Prep X: fp32 X -> single fp16 image, pre-swizzled & tile-ordered.
// ============================================================================
__global__ void prep_x_kernel(const float* __restrict__ X) {
    int g  = blockIdx.x * 256 + threadIdx.x;   // 8192*512 chunks
    int n  = g >> 9;
    int k0 = (g & 511) << 3;
    const float4* xp = reinterpret_cast<const float4*>(X + (size_t)n * D_IN + k0);
    float4 a = xp[0], b = xp[1];
    union { __half h[8]; uint4 u; } hi;
    hi.h[0] = __float2half_rn(a.x); hi.h[1] = __float2half_rn(a.y);
    hi.h[2] = __float2half_rn(a.z); hi.h[3] = __float2half_rn(a.w);
    hi.h[4] = __float2half_rn(b.x); hi.h[5] = __float2half_rn(b.y);
    hi.h[6] = __float2half_rn(b.z); hi.h[7] = __float2half_rn(b.w);
    int mt = n >> 7, m = n & 127, ks = k0 >> 6, kk = k0 & 63;
    uint32_t off = (uint32_t)(m * 128 + kk * 2);
    uint32_t sw  = off ^ ((off >> 3) & 0x70u);
    *reinterpret_cast<uint4*>(g_A + (size_t)(mt * 64 + ks) * A_STAGE + sw) = hi.u;
}

// ============================================================================
// Prep W: W' = (W_nf4 * c1) * c_kbit2 + L1@L2, transposed to N-major [d][k],
// fp16, pre-swizzled into 128-wide n-panels. Block tile: 64 k x 32 d.
// ============================================================================
__global__ void prep_w_kernel(const float* __restrict__ Wn, const float* __restrict__ c1p,
                              const float* __restrict__ ck, const float* __restrict__ L1,
                              const float* __restrict__ L2) {
    __shared__ float sL1[64 * 16];
    __shared__ float sL2[16 * 32];
    __shared__ __align__(16) __half sOut[32 * 64];
    const int t  = threadIdx.x;
    const int k0 = blockIdx.y * 64;
    const int d0 = blockIdx.x * 32;
    const float c1 = __ldg(c1p);

    for (int i = t; i < 1024; i += 256) sL1[i] = L1[(size_t)k0 * 16 + i];
    for (int i = t; i < 512;  i += 256) sL2[i] = L2[(size_t)(i >> 5) * D_OUT + d0 + (i & 31)];

    const int dd = t & 31;
    float wv[8];
#pragma unroll
    for (int i = 0; i < 8; i++) {
        int k = (t >> 5) + i * 8;
        size_t gi = (size_t)(k0 + k) * D_OUT + d0 + dd;
        wv[i] = (Wn[gi] * c1) * ck[gi];   // match reference mul order
    }
    __syncthreads();
#pragma unroll
    for (int i = 0; i < 8; i++) {
        int k = (t >> 5) + i * 8;
        float acc = wv[i];
#pragma unroll
        for (int r = 0; r < 16; r++) acc += sL1[k * 16 + r] * sL2[r * 32 + dd];
        sOut[dd * 64 + k] = __float2half_rn(acc);
    }
    __syncthreads();
    const int od = t >> 3, c = t & 7;
    uint4 v = *reinterpret_cast<uint4*>(&sOut[od * 64 + c * 8]);
    int ntile = blockIdx.x >> 2;                 // 128-wide panel index
    int nloc  = ((blockIdx.x & 3) << 5) + od;    // 0..127 within panel
    uint32_t off = (uint32_t)(nloc * 128 + c * 16);
    uint32_t sw  = off ^ ((off >> 3) & 0x70u);
    *reinterpret_cast<uint4*>(g_B + (size_t)(ntile * 64 + blockIdx.y) * B_STAGE + sw) = v;
}

// ============================================================================
// GEMM: Y[8192,4096] = Xh @ W' via mma.sync.m16n8k16 (HMMA).
// CTA tile 128x128, warp grid 2(m)x4(n) of 64x32 warp tiles.
// 3-stage cp.async pipeline, one __syncthreads per K-iter,
// 2 CTAs/SM for cross-CTA latency hiding (the R6 lesson: occupancy,
// not deeper pipelining, is what covers the barrier/LDSM head).
// ============================================================================
static __device__ __forceinline__ void load_stage(uint32_t sA, uint32_t sB,
                                                  const uint8_t* gA, const uint8_t* gB,
                                                  int tid) {
#pragma unroll
    for (int i = 0; i < 4; i++) {
        uint32_t o = (uint32_t)(tid + i * 256) * 16u;
        cp16(sA + o, gA + o);
        cp16(sB + o, gB + o);
    }
}

__global__ void __launch_bounds__(256, 2) qlora_gemm(float* __restrict__ Y) {
    extern __shared__ __align__(16) uint8_t smem[];
    const int tid  = threadIdx.x;
    const int wid  = tid >> 5;
    const int lane = tid & 31;
    const int nt = blockIdx.x;     // n-tile fastest -> W' panel reuse in L2
    const int mt = blockIdx.y;

    const int wm = wid >> 2;       // 0..1  (m offset wm*64)
    const int wn = wid & 3;        // 0..3  (n offset wn*32)

    uint32_t base   = smem_u32(smem);
    uint32_t stage0 = (base + 1023u) & ~1023u;

    // SW128 within a 128B-row tile reduces to: addr = row*128 + (kb ^ ((row&7)*16)).
    const int lr = lane & 15;
    const int lk = (lane >> 4) * 16;
    const int xm = (lr & 7) * 16;
    uint32_t aRowOff[4], bRowOff[2];
#pragma unroll
    for (int mi = 0; mi < 4; mi++) aRowOff[mi] = (uint32_t)((wm * 64 + mi * 16 + lr) * 128);
#pragma unroll
    for (int nj = 0; nj < 2; nj++) bRowOff[nj] = (uint32_t)((wn * 32 + nj * 16 + lr) * 128);

    float acc[4][4][4];
#pragma unroll
    for (int mi = 0; mi < 4; mi++)
#pragma unroll
        for (int nj = 0; nj < 4; nj++)
#pragma unroll
            for (int c = 0; c < 4; c++) acc[mi][nj][c] = 0.0f;

    // prologue: fill NSTAGE-1 = 2 stages
#pragma unroll
    for (int s = 0; s < NSTAGE - 1; s++) {
        const uint8_t* gA = g_A + (size_t)(mt * 64 + s) * A_STAGE;
        const uint8_t* gB = g_B + (size_t)(nt * 64 + s) * B_STAGE;
        uint32_t sA = stage0 + s * STAGE_BYTES;
        load_stage(sA, sA + A_STAGE, gA, gB, tid);
        asm volatile("cp.async.commit_group;" ::: "memory");
    }

    int rbuf = 0, wbuf = NSTAGE - 1;
    for (int it = 0; it < K_ITERS; ++it) {
        uint32_t sA = stage0 + rbuf * STAGE_BYTES;
        uint32_t sB = sA + A_STAGE;
        asm volatile("cp.async.wait_group %0;" :: "n"(NSTAGE - 2) : "memory");
        __syncthreads();   // read-stage visible; wbuf (read last iter) is free

        // refill: stage it+NSTAGE-1 into wbuf
        int nx = it + NSTAGE - 1;
        if (nx < K_ITERS) {
            const uint8_t* gA = g_A + (size_t)(mt * 64 + nx) * A_STAGE;
            const uint8_t* gB = g_B + (size_t)(nt * 64 + nx) * B_STAGE;
            uint32_t wA = stage0 + wbuf * STAGE_BYTES;
            load_stage(wA, wA + A_STAGE, gA, gB, tid);
        }
        asm volatile("cp.async.commit_group;" ::: "memory");

#pragma unroll
        for (int ks = 0; ks < 4; ks++) {
            uint32_t kb = (uint32_t)((ks * 32 + lk) ^ xm);
            uint32_t a[4][4], bq[2][4];
#pragma unroll
            for (int mi = 0; mi < 4; mi++) ldsm4(a[mi],  sA + aRowOff[mi] + kb);
#pragma unroll
            for (int nj = 0; nj < 2; nj++) ldsm4(bq[nj], sB + bRowOff[nj] + kb);
#pragma unroll
            for (int mi = 0; mi < 4; mi++)
#pragma unroll
                for (int nj = 0; nj < 2; nj++) {
                    mma16816(acc[mi][2 * nj],     a[mi], bq[nj][0], bq[nj][2]);
                    mma16816(acc[mi][2 * nj + 1], a[mi], bq[nj][1], bq[nj][3]);
                }
        }

        wbuf = rbuf;
        rbuf++; if (rbuf == NSTAGE) rbuf = 0;
    }

    // epilogue: direct fp32 stores (float2, 32B-sector aligned per lane quad)
    float* yBase = Y + (size_t)(mt * 128 + wm * 64) * D_OUT + nt * 128 + wn * 32;
    const int qr = lane >> 2;
    const int qc = (lane & 3) * 2;
#pragma unroll
    for (int mi = 0; mi < 4; mi++) {
        float* y0 = yBase + (size_t)(mi * 16 + qr) * D_OUT + qc;
        float* y1 = y0 + (size_t)8 * D_OUT;
#pragma unroll
        for (int nj = 0; nj < 4; nj++) {
            *reinterpret_cast<float2*>(y0 + nj * 8) = make_float2(acc[mi][nj][0], acc[mi][nj][1]);
            *reinterpret_cast<float2*>(y1 + nj * 8) = make_float2(acc[mi][nj][2], acc[mi][nj][3]);
        }
    }
}

// ============================================================================
extern "C" void kernel_launch(void* const* d_in, const int* in_sizes, int n_in,
                              void* d_out, int out_size) {
    (void)in_sizes; (void)n_in; (void)out_size;
    const float* X  = (const float*)d_in[0];
    const float* Wn = (const float*)d_in[1];
    const float* c1 = (const float*)d_in[2];
    const float* ck = (const float*)d_in[3];
    const float* L1 = (const float*)d_in[4];
    const float* L2 = (const float*)d_in[5];
    float* Y = (float*)d_out;

    prep_x_kernel<<<16384, 256>>>(X);
    prep_w_kernel<<<dim3(128, 64), 256>>>(Wn, c1, ck, L1, L2);
    cudaFuncSetAttribute(qlora_gemm, cudaFuncAttributeMaxDynamicSharedMemorySize, SMEM_DYN);
    qlora_gemm<<<dim3(N_TILES, M_TILES), 256, SMEM_DYN>>>(Y);
}

// round 13
// speedup vs baseline: 1.0988x; 1.0179x over previous
#include <cuda_runtime.h>
#include <cuda_fp16.h>
#include <cstdint>
#include <cstddef>

// ---------------- Problem dims ----------------
#define N_ROWS 8192
#define D_IN   4096
#define D_OUT  4096

// ---------------- GEMM tiling -----------------
#define TM 128
#define TN 128
#define TK 64
#define M_TILES 64      // 8192/128
#define N_TILES 32      // 4096/128
#define K_ITERS 64      // 4096/64 (single fp16 X image)
#define A_STAGE 16384   // TM*TK*2 bytes (fp16)
#define B_STAGE 16384   // TN*TK*2 bytes (fp16)
#define STAGE_BYTES 32768
#define NSTAGE 3
#define SMEM_DYN 99840  // 3*32768 + mbarriers + 1024-align slack (x2 CTAs fits 227KB)

// Pre-swizzled, tile-ordered operand images (scratch via __device__ globals).
__device__ __align__(1024) uint8_t g_A[(size_t)M_TILES * K_ITERS * A_STAGE]; // 64 MB
__device__ __align__(1024) uint8_t g_B[(size_t)N_TILES * K_ITERS * B_STAGE]; // 32 MB

// ---------------- helpers ----------------
static __device__ __forceinline__ uint32_t smem_u32(const void* p) {
    uint32_t a;
    asm("{ .reg .u64 t; cvta.to.shared.u64 t, %1; cvt.u32.u64 %0, t; }"
        : "=r"(a) : "l"(p));
    return a;
}

static __device__ __forceinline__ void cp16(uint32_t dst, const void* src) {
    asm volatile("cp.async.cg.shared.global [%0], [%1], 16;"
                 :: "r"(dst), "l"(src) : "memory");
}

static __device__ __forceinline__ void ldsm4(uint32_t (&r)[4], uint32_t addr) {
    asm volatile("ldmatrix.sync.aligned.m8n8.x4.shared.b16 {%0,%1,%2,%3}, [%4];"
                 : "=r"(r[0]), "=r"(r[1]), "=r"(r[2]), "=r"(r[3]) : "r"(addr));
}

static __device__ __forceinline__ void mma16816(float* d, const uint32_t* a,
                                                uint32_t b0, uint32_t b1) {
    asm volatile(
        "mma.sync.aligned.m16n8k16.row.col.f32.f16.f16.f32 "
        "{%0,%1,%2,%3}, {%4,%5,%6,%7}, {%8,%9}, {%0,%1,%2,%3};"
        : "+f"(d[0]), "+f"(d[1]), "+f"(d[2]), "+f"(d[3])
        : "r"(a[0]), "r"(a[1]), "r"(a[2]), "r"(a[3]), "r"(b0), "r"(b1));
}

static __device__ __forceinline__ void mbar_init(uint32_t addr, uint32_t cnt) {
    asm volatile("mbarrier.init.shared.b64 [%0], %1;" :: "r"(addr), "r"(cnt) : "memory");
}
static __device__ __forceinline__ void mbar_arrive(uint32_t addr) {
    asm volatile("mbarrier.arrive.shared.b64 _, [%0];" :: "r"(addr) : "memory");
}
static __device__ __forceinline__ void cp_arrive(uint32_t addr) {
    asm volatile("cp.async.mbarrier.arrive.noinc.shared.b64 [%0];" :: "r"(addr) : "memory");
}
// consumer wait: acquire (orders subsequent LDSM against producer cp.async writes)
static __device__ __forceinline__ void mbar_wait_acq(uint32_t addr, uint32_t parity) {
    asm volatile(
        "{\n\t.reg .pred P;\n"
        "LWA%=:\n\t"
        "mbarrier.try_wait.parity.acquire.cta.shared::cta.b64 P, [%0], %1;\n\t"
        "@!P bra LWA%=;\n\t}"
        :: "r"(addr), "r"(parity) : "memory");
}
// producer wait: relaxed (subsequent accesses are async-proxy cp.async writes)
static __device__ __forceinline__ void mbar_wait_rlx(uint32_t addr, uint32_t parity) {
    asm volatile(
        "{\n\t.reg .pred P;\n"
        "LWR%=:\n\t"
        "mbarrier.try_wait.parity.relaxed.cta.shared::cta.b64 P, [%0], %1;\n\t"
        "@!P bra LWR%=;\n\t}"
        :: "r"(addr), "r"(parity) : "memory");
}

// ============================================================================
// Prep X: fp32 X -> single fp16 image, pre-swizzled & tile-ordered.
// ============================================================================
__global__ void prep_x_kernel(const float* __restrict__ X) {
    int g  = blockIdx.x * 256 + threadIdx.x;   // 8192*512 chunks
    int n  = g >> 9;
    int k0 = (g & 511) << 3;
    const float4* xp = reinterpret_cast<const float4*>(X + (size_t)n * D_IN + k0);
    float4 a = xp[0], b = xp[1];
    union { __half h[8]; uint4 u; } hi;
    hi.h[0] = __float2half_rn(a.x); hi.h[1] = __float2half_rn(a.y);
    hi.h[2] = __float2half_rn(a.z); hi.h[3] = __float2half_rn(a.w);
    hi.h[4] = __float2half_rn(b.x); hi.h[5] = __float2half_rn(b.y);
    hi.h[6] = __float2half_rn(b.z); hi.h[7] = __float2half_rn(b.w);
    int mt = n >> 7, m = n & 127, ks = k0 >> 6, kk = k0 & 63;
    uint32_t off = (uint32_t)(m * 128 + kk * 2);
    uint32_t sw  = off ^ ((off >> 3) & 0x70u);
    *reinterpret_cast<uint4*>(g_A + (size_t)(mt * 64 + ks) * A_STAGE + sw) = hi.u;
}

// ============================================================================
// Prep W: W' = (W_nf4 * c1) * c_kbit2 + L1@L2, transposed to N-major [d][k],
// fp16, pre-swizzled into 128-wide n-panels. Block tile: 64 k x 32 d.
// ============================================================================
__global__ void prep_w_kernel(const float* __restrict__ Wn, const float* __restrict__ c1p,
                              const float* __restrict__ ck, const float* __restrict__ L1,
                              const float* __restrict__ L2) {
    __shared__ float sL1[64 * 16];
    __shared__ float sL2[16 * 32];
    __shared__ __align__(16) __half sOut[32 * 64];
    const int t  = threadIdx.x;
    const int k0 = blockIdx.y * 64;
    const int d0 = blockIdx.x * 32;
    const float c1 = __ldg(c1p);

    for (int i = t; i < 1024; i += 256) sL1[i] = L1[(size_t)k0 * 16 + i];
    for (int i = t; i < 512;  i += 256) sL2[i] = L2[(size_t)(i >> 5) * D_OUT + d0 + (i & 31)];

    const int dd = t & 31;
    float wv[8];
#pragma unroll
    for (int i = 0; i < 8; i++) {
        int k = (t >> 5) + i * 8;
        size_t gi = (size_t)(k0 + k) * D_OUT + d0 + dd;
        wv[i] = (Wn[gi] * c1) * ck[gi];   // match reference mul order
    }
    __syncthreads();
#pragma unroll
    for (int i = 0; i < 8; i++) {
        int k = (t >> 5) + i * 8;
        float acc = wv[i];
#pragma unroll
        for (int r = 0; r < 16; r++) acc += sL1[k * 16 + r] * sL2[r * 32 + dd];
        sOut[dd * 64 + k] = __float2half_rn(acc);
    }
    __syncthreads();
    const int od = t >> 3, c = t & 7;
    uint4 v = *reinterpret_cast<uint4*>(&sOut[od * 64 + c * 8]);
    int ntile = blockIdx.x >> 2;                 // 128-wide panel index
    int nloc  = ((blockIdx.x & 3) << 5) + od;    // 0..127 within panel
    uint32_t off = (uint32_t)(nloc * 128 + c * 16);
    uint32_t sw  = off ^ ((off >> 3) & 0x70u);
    *reinterpret_cast<uint4*>(g_B + (size_t)(ntile * 64 + blockIdx.y) * B_STAGE + sw) = v;
}

// ============================================================================
// GEMM: Y[8192,4096] = Xh @ W' via mma.sync.m16n8k16 (HMMA).
// CTA tile 128x128, warp grid 2(m)x4(n), 2 CTAs/SM.
// mbarrier producer-consumer pipeline (full count=256 via
// cp.async.mbarrier.arrive; empty count=8, lane0/warp): NO CTA-wide
// rendezvous in the main loop -> warps may skew ~1-2 iters, smearing
// the per-iter memory-wait head that __syncthreads used to synchronize.
// ============================================================================
static __device__ __forceinline__ void load_stage(uint32_t sA, uint32_t sB,
                                                  const uint8_t* gA, const uint8_t* gB,
                                                  int tid) {
#pragma unroll
    for (int i = 0; i < 4; i++) {
        uint32_t o = (uint32_t)(tid + i * 256) * 16u;
        cp16(sA + o, gA + o);
        cp16(sB + o, gB + o);
    }
}

__global__ void __launch_bounds__(256, 2) qlora_gemm(float* __restrict__ Y) {
    extern __shared__ __align__(16) uint8_t smem[];
    const int tid  = threadIdx.x;
    const int wid  = tid >> 5;
    const int lane = tid & 31;
    const int nt = blockIdx.x;     // n-tile fastest -> W' panel reuse in L2
    const int mt = blockIdx.y;

    const int wm = wid >> 2;       // 0..1  (m offset wm*64)
    const int wn = wid & 3;        // 0..3  (n offset wn*32)

    uint32_t base   = smem_u32(smem);
    uint32_t stage0 = (base + 64u + 1023u) & ~1023u;   // >=64B gap below for mbarriers
    uint32_t mb     = base;                             // full[s]=mb+16s, empty[s]=mb+16s+8

    if (tid == 0) {
#pragma unroll
        for (int s = 0; s < NSTAGE; s++) {
            mbar_init(mb + 16u * s,      256u);  // full: per-thread cp completion
            mbar_init(mb + 16u * s + 8u,   8u);  // empty: lane0 per warp
        }
    }
    __syncthreads();   // one-time: barriers visible

    // SW128 within a 128B-row tile reduces to: addr = row*128 + (kb ^ ((row&7)*16)).
    const int lr = lane & 15;
    const int lk = (lane >> 4) * 16;
    const int xm = (lr & 7) * 16;
    uint32_t aRowOff[4], bRowOff[2];
#pragma unroll
    for (int mi = 0; mi < 4; mi++) aRowOff[mi] = (uint32_t)((wm * 64 + mi * 16 + lr) * 128);
#pragma unroll
    for (int nj = 0; nj < 2; nj++) bRowOff[nj] = (uint32_t)((wn * 32 + nj * 16 + lr) * 128);

    float acc[4][4][4];
#pragma unroll
    for (int mi = 0; mi < 4; mi++)
#pragma unroll
        for (int nj = 0; nj < 4; nj++)
#pragma unroll
            for (int c = 0; c < 4; c++) acc[mi][nj][c] = 0.0f;

    // prologue: fill stages 0,1 (no empty-wait needed on first fill)
#pragma unroll
    for (int s = 0; s < NSTAGE - 1; s++) {
        const uint8_t* gA = g_A + (size_t)(mt * 64 + s) * A_STAGE;
        const uint8_t* gB = g_B + (size_t)(nt * 64 + s) * B_STAGE;
        uint32_t sA = stage0 + s * STAGE_BYTES;
        load_stage(sA, sA + A_STAGE, gA, gB, tid);
        cp_arrive(mb + 16u * s);
    }

    uint32_t fp = 0u;   // consumer full-phase (flips after it%3==2)
    uint32_t ep = 1u;   // producer empty-phase (first wait passes; flips after it%3==0)
    int rbuf = 0, wbuf = NSTAGE - 1;
    for (int it = 0; it < K_ITERS; ++it) {
        uint32_t sA = stage0 + rbuf * STAGE_BYTES;
        uint32_t sB = sA + A_STAGE;
        mbar_wait_acq(mb + 16u * rbuf, fp);     // all threads' copies landed

#pragma unroll
        for (int ks = 0; ks < 4; ks++) {
            uint32_t kb = (uint32_t)((ks * 32 + lk) ^ xm);
            uint32_t a[4][4], bq[2][4];
#pragma unroll
            for (int mi = 0; mi < 4; mi++) ldsm4(a[mi],  sA + aRowOff[mi] + kb);
#pragma unroll
            for (int nj = 0; nj < 2; nj++) ldsm4(bq[nj], sB + bRowOff[nj] + kb);
#pragma unroll
            for (int mi = 0; mi < 4; mi++)
#pragma unroll
                for (int nj = 0; nj < 2; nj++) {
                    mma16816(acc[mi][2 * nj],     a[mi], bq[nj][0], bq[nj][2]);
                    mma16816(acc[mi][2 * nj + 1], a[mi], bq[nj][1], bq[nj][3]);
                }
        }
        // release: this warp's HMMAs issued => its LDSM smem reads completed
        if (lane == 0) mbar_arrive(mb + 16u * rbuf + 8u);

        // refill stage (it+2) into wbuf, gated on all warps having released it
        int nx = it + NSTAGE - 1;
        if (nx < K_ITERS) {
            mbar_wait_rlx(mb + 16u * wbuf + 8u, ep);
            const uint8_t* gA = g_A + (size_t)(mt * 64 + nx) * A_STAGE;
            const uint8_t* gB = g_B + (size_t)(nt * 64 + nx) * B_STAGE;
            uint32_t wA = stage0 + wbuf * STAGE_BYTES;
            load_stage(wA, wA + A_STAGE, gA, gB, tid);
            cp_arrive(mb + 16u * wbuf);
        }

        // phase bookkeeping (verified against fill/consume sequences)
        int r3 = it - (it / 3) * 3;
        if (r3 == 2) fp ^= 1u;
        if (r3 == 0) ep ^= 1u;
        rbuf++; if (rbuf == NSTAGE) rbuf = 0;
        wbuf++; if (wbuf == NSTAGE) wbuf = 0;
    }

    // epilogue: direct fp32 stores (float2, 32B-sector aligned per lane quad)
    float* yBase = Y + (size_t)(mt * 128 + wm * 64) * D_OUT + nt * 128 + wn * 32;
    const int qr = lane >> 2;
    const int qc = (lane & 3) * 2;
#pragma unroll
    for (int mi = 0; mi < 4; mi++) {
        float* y0 = yBase + (size_t)(mi * 16 + qr) * D_OUT + qc;
        float* y1 = y0 + (size_t)8 * D_OUT;
#pragma unroll
        for (int nj = 0; nj < 4; nj++) {
            *reinterpret_cast<float2*>(y0 + nj * 8) = make_float2(acc[mi][nj][0], acc[mi][nj][1]);
            *reinterpret_cast<float2*>(y1 + nj * 8) = make_float2(acc[mi][nj][2], acc[mi][nj][3]);
        }
    }
}

// ============================================================================
extern "C" void kernel_launch(void* const* d_in, const int* in_sizes, int n_in,
                              void* d_out, int out_size) {
    (void)in_sizes; (void)n_in; (void)out_size;
    const float* X  = (const float*)d_in[0];
    const float* Wn = (const float*)d_in[1];
    const float* c1 = (const float*)d_in[2];
    const float* ck = (const float*)d_in[3];
    const float* L1 = (const float*)d_in[4];
    const float* L2 = (const float*)d_in[5];
    float* Y = (float*)d_out;

    prep_x_kernel<<<16384, 256>>>(X);
    prep_w_kernel<<<dim3(128, 64), 256>>>(Wn, c1, ck, L1, L2);
    cudaFuncSetAttribute(qlora_gemm, cudaFuncAttributeMaxDynamicSharedMemorySize, SMEM_DYN);
    qlora_gemm<<<dim3(N_TILES, M_TILES), 256, SMEM_DYN>>>(Y);
}

// round 14
// speedup vs baseline: 1.1315x; 1.0298x over previous
#include <cuda_runtime.h>
#include <cuda_fp16.h>
#include <cstdint>
#include <cstddef>

// ---------------- Problem dims ----------------
#define N_ROWS 8192
#define D_IN   4096
#define D_OUT  4096

// ---------------- GEMM tiling -----------------
#define TM 128
#define TN 256
#define TK 64
#define M_TILES 64      // 8192/128
#define N_TILES 16      // 4096/256
#define K_ITERS 64      // 4096/64 (single fp16 X image)
#define A_STAGE 16384   // TM*TK*2 bytes (fp16)
#define B_STAGE 32768   // TN*TK*2 bytes (fp16)
#define STAGE_BYTES 49152
#define NSTAGE 4
#define SMEM_DYN 197632 // 4*49152 + mbarriers + 1024-align slack (1 CTA/SM)

// Pre-swizzled, tile-ordered operand images (scratch via __device__ globals).
__device__ __align__(1024) uint8_t g_A[(size_t)M_TILES * K_ITERS * A_STAGE]; // 64 MB
__device__ __align__(1024) uint8_t g_B[(size_t)N_TILES * K_ITERS * B_STAGE]; // 32 MB

// ---------------- helpers ----------------
static __device__ __forceinline__ uint32_t smem_u32(const void* p) {
    uint32_t a;
    asm("{ .reg .u64 t; cvta.to.shared.u64 t, %1; cvt.u32.u64 %0, t; }"
        : "=r"(a) : "l"(p));
    return a;
}

static __device__ __forceinline__ void cp16(uint32_t dst, const void* src) {
    asm volatile("cp.async.cg.shared.global [%0], [%1], 16;"
                 :: "r"(dst), "l"(src) : "memory");
}

static __device__ __forceinline__ void ldsm4(uint32_t (&r)[4], uint32_t addr) {
    asm volatile("ldmatrix.sync.aligned.m8n8.x4.shared.b16 {%0,%1,%2,%3}, [%4];"
                 : "=r"(r[0]), "=r"(r[1]), "=r"(r[2]), "=r"(r[3]) : "r"(addr));
}

static __device__ __forceinline__ void mma16816(float* d, const uint32_t* a,
                                                uint32_t b0, uint32_t b1) {
    asm volatile(
        "mma.sync.aligned.m16n8k16.row.col.f32.f16.f16.f32 "
        "{%0,%1,%2,%3}, {%4,%5,%6,%7}, {%8,%9}, {%0,%1,%2,%3};"
        : "+f"(d[0]), "+f"(d[1]), "+f"(d[2]), "+f"(d[3])
        : "r"(a[0]), "r"(a[1]), "r"(a[2]), "r"(a[3]), "r"(b0), "r"(b1));
}

static __device__ __forceinline__ void mbar_init(uint32_t addr, uint32_t cnt) {
    asm volatile("mbarrier.init.shared.b64 [%0], %1;" :: "r"(addr), "r"(cnt) : "memory");
}
static __device__ __forceinline__ void mbar_arrive(uint32_t addr) {
    asm volatile("mbarrier.arrive.shared.b64 _, [%0];" :: "r"(addr) : "memory");
}
static __device__ __forceinline__ void cp_arrive(uint32_t addr) {
    asm volatile("cp.async.mbarrier.arrive.noinc.shared.b64 [%0];" :: "r"(addr) : "memory");
}
// consumer wait: acquire (orders subsequent LDSM against producer cp.async writes)
static __device__ __forceinline__ void mbar_wait_acq(uint32_t addr, uint32_t parity) {
    asm volatile(
        "{\n\t.reg .pred P;\n"
        "LWA%=:\n\t"
        "mbarrier.try_wait.parity.acquire.cta.shared::cta.b64 P, [%0], %1;\n\t"
        "@!P bra LWA%=;\n\t}"
        :: "r"(addr), "r"(parity) : "memory");
}
// producer wait: relaxed (subsequent accesses are async-proxy cp.async writes)
static __device__ __forceinline__ void mbar_wait_rlx(uint32_t addr, uint32_t parity) {
    asm volatile(
        "{\n\t.reg .pred P;\n"
        "LWR%=:\n\t"
        "mbarrier.try_wait.parity.relaxed.cta.shared::cta.b64 P, [%0], %1;\n\t"
        "@!P bra LWR%=;\n\t}"
        :: "r"(addr), "r"(parity) : "memory");
}

// ============================================================================
// Prep X: fp32 X -> single fp16 image, pre-swizzled & tile-ordered.
// ============================================================================
__global__ void prep_x_kernel(const float* __restrict__ X) {
    int g  = blockIdx.x * 256 + threadIdx.x;   // 8192*512 chunks
    int n  = g >> 9;
    int k0 = (g & 511) << 3;
    const float4* xp = reinterpret_cast<const float4*>(X + (size_t)n * D_IN + k0);
    float4 a = xp[0], b = xp[1];
    union { __half h[8]; uint4 u; } hi;
    hi.h[0] = __float2half_rn(a.x); hi.h[1] = __float2half_rn(a.y);
    hi.h[2] = __float2half_rn(a.z); hi.h[3] = __float2half_rn(a.w);
    hi.h[4] = __float2half_rn(b.x); hi.h[5] = __float2half_rn(b.y);
    hi.h[6] = __float2half_rn(b.z); hi.h[7] = __float2half_rn(b.w);
    int mt = n >> 7, m = n & 127, ks = k0 >> 6, kk = k0 & 63;
    uint32_t off = (uint32_t)(m * 128 + kk * 2);
    uint32_t sw  = off ^ ((off >> 3) & 0x70u);
    *reinterpret_cast<uint4*>(g_A + (size_t)(mt * 64 + ks) * A_STAGE + sw) = hi.u;
}

// ============================================================================
// Prep W: W' = (W_nf4 * c1) * c_kbit2 + L1@L2, transposed to N-major [d][k],
// fp16, pre-swizzled into 256-wide n-panels. Block tile: 64 k x 32 d.
// ============================================================================
__global__ void prep_w_kernel(const float* __restrict__ Wn, const float* __restrict__ c1p,
                              const float* __restrict__ ck, const float* __restrict__ L1,
                              const float* __restrict__ L2) {
    __shared__ float sL1[64 * 16];
    __shared__ float sL2[16 * 32];
    __shared__ __align__(16) __half sOut[32 * 64];
    const int t  = threadIdx.x;
    const int k0 = blockIdx.y * 64;
    const int d0 = blockIdx.x * 32;
    const float c1 = __ldg(c1p);

    for (int i = t; i < 1024; i += 256) sL1[i] = L1[(size_t)k0 * 16 + i];
    for (int i = t; i < 512;  i += 256) sL2[i] = L2[(size_t)(i >> 5) * D_OUT + d0 + (i & 31)];

    const int dd = t & 31;
    float wv[8];
#pragma unroll
    for (int i = 0; i < 8; i++) {
        int k = (t >> 5) + i * 8;
        size_t gi = (size_t)(k0 + k) * D_OUT + d0 + dd;
        wv[i] = (Wn[gi] * c1) * ck[gi];   // match reference mul order
    }
    __syncthreads();
#pragma unroll
    for (int i = 0; i < 8; i++) {
        int k = (t >> 5) + i * 8;
        float acc = wv[i];
#pragma unroll
        for (int r = 0; r < 16; r++) acc += sL1[k * 16 + r] * sL2[r * 32 + dd];
        sOut[dd * 64 + k] = __float2half_rn(acc);
    }
    __syncthreads();
    const int od = t >> 3, c = t & 7;
    uint4 v = *reinterpret_cast<uint4*>(&sOut[od * 64 + c * 8]);
    int ntile = blockIdx.x >> 3;                 // 256-wide panel index
    int nloc  = ((blockIdx.x & 7) << 5) + od;    // 0..255 within panel
    uint32_t off = (uint32_t)(nloc * 128 + c * 16);
    uint32_t sw  = off ^ ((off >> 3) & 0x70u);
    *reinterpret_cast<uint4*>(g_B + (size_t)(ntile * 64 + blockIdx.y) * B_STAGE + sw) = v;
}

// ============================================================================
// GEMM: Y[8192,4096] = Xh @ W' via mma.sync.m16n8k16 (HMMA).
// CTA tile 128x256, warp grid 2(m)x4(n) of 64x64 warp tiles (halves smem
// LDSM traffic per MAC vs 64x32 -> back under the HMMA floor), 1 CTA/SM.
// 4-stage mbarrier producer-consumer pipeline: no CTA-wide rendezvous,
// warps skew up to ~3 iters to smear the memory-wait head (R13 lesson).
// ============================================================================
static __device__ __forceinline__ void load_stage(uint32_t sA, uint32_t sB,
                                                  const uint8_t* gA, const uint8_t* gB,
                                                  int tid) {
#pragma unroll
    for (int i = 0; i < 4; i++) {
        uint32_t o = (uint32_t)(tid + i * 256) * 16u;
        cp16(sA + o, gA + o);
    }
#pragma unroll
    for (int i = 0; i < 8; i++) {
        uint32_t o = (uint32_t)(tid + i * 256) * 16u;
        cp16(sB + o, gB + o);
    }
}

__global__ void __launch_bounds__(256, 1) qlora_gemm(float* __restrict__ Y) {
    extern __shared__ __align__(16) uint8_t smem[];
    const int tid  = threadIdx.x;
    const int wid  = tid >> 5;
    const int lane = tid & 31;
    const int nt = blockIdx.x;     // n-tile fastest -> W' panel reuse in L2
    const int mt = blockIdx.y;

    const int wm = wid >> 2;       // 0..1  (m offset wm*64)
    const int wn = wid & 3;        // 0..3  (n offset wn*64)

    uint32_t base   = smem_u32(smem);
    uint32_t stage0 = (base + 128u + 1023u) & ~1023u;  // gap below for mbarriers
    uint32_t mb     = base;                            // full[s]=mb+16s, empty[s]=+8

    if (tid == 0) {
#pragma unroll
        for (int s = 0; s < NSTAGE; s++) {
            mbar_init(mb + 16u * s,      256u);  // full: per-thread cp completion
            mbar_init(mb + 16u * s + 8u,   8u);  // empty: lane0 per warp
        }
    }
    __syncthreads();   // one-time: barriers visible

    // SW128 within a 128B-row tile reduces to: addr = row*128 + (kb ^ ((row&7)*16)).
    const int lr = lane & 15;
    const int lk = (lane >> 4) * 16;
    const int xm = (lr & 7) * 16;
    uint32_t aRowOff[4], bRowOff[4];
#pragma unroll
    for (int mi = 0; mi < 4; mi++) aRowOff[mi] = (uint32_t)((wm * 64 + mi * 16 + lr) * 128);
#pragma unroll
    for (int nj = 0; nj < 4; nj++) bRowOff[nj] = (uint32_t)((wn * 64 + nj * 16 + lr) * 128);

    float acc[4][8][4];
#pragma unroll
    for (int mi = 0; mi < 4; mi++)
#pragma unroll
        for (int nj = 0; nj < 8; nj++)
#pragma unroll
            for (int c = 0; c < 4; c++) acc[mi][nj][c] = 0.0f;

    // prologue: fill stages 0..2 (no empty-wait needed on first fill)
#pragma unroll
    for (int s = 0; s < NSTAGE - 1; s++) {
        const uint8_t* gA = g_A + (size_t)(mt * 64 + s) * A_STAGE;
        const uint8_t* gB = g_B + (size_t)(nt * 64 + s) * B_STAGE;
        uint32_t sA = stage0 + s * STAGE_BYTES;
        load_stage(sA, sA + A_STAGE, gA, gB, tid);
        cp_arrive(mb + 16u * s);
    }

    uint32_t fp = 0u;   // consumer full-phase: flips after (it&3)==3
    uint32_t ep = 1u;   // producer empty-phase: first wait passes; flips after (it&3)==0
    int rbuf = 0, wbuf = NSTAGE - 1;
    for (int it = 0; it < K_ITERS; ++it) {
        uint32_t sA = stage0 + rbuf * STAGE_BYTES;
        uint32_t sB = sA + A_STAGE;
        mbar_wait_acq(mb + 16u * rbuf, fp);     // all threads' copies landed

#pragma unroll
        for (int ks = 0; ks < 4; ks++) {
            uint32_t kb = (uint32_t)((ks * 32 + lk) ^ xm);
            uint32_t a[4][4], bq[4][4];
#pragma unroll
            for (int mi = 0; mi < 4; mi++) ldsm4(a[mi],  sA + aRowOff[mi] + kb);
#pragma unroll
            for (int nj = 0; nj < 4; nj++) ldsm4(bq[nj], sB + bRowOff[nj] + kb);
#pragma unroll
            for (int mi = 0; mi < 4; mi++)
#pragma unroll
                for (int nj = 0; nj < 4; nj++) {
                    mma16816(acc[mi][2 * nj],     a[mi], bq[nj][0], bq[nj][2]);
                    mma16816(acc[mi][2 * nj + 1], a[mi], bq[nj][1], bq[nj][3]);
                }
        }
        // release: this warp's HMMAs issued => its LDSM smem reads completed
        if (lane == 0) mbar_arrive(mb + 16u * rbuf + 8u);

        // refill stage (it+3) into wbuf, gated on all warps having released it
        int nx = it + NSTAGE - 1;
        if (nx < K_ITERS) {
            mbar_wait_rlx(mb + 16u * wbuf + 8u, ep);
            const uint8_t* gA = g_A + (size_t)(mt * 64 + nx) * A_STAGE;
            const uint8_t* gB = g_B + (size_t)(nt * 64 + nx) * B_STAGE;
            uint32_t wA = stage0 + wbuf * STAGE_BYTES;
            load_stage(wA, wA + A_STAGE, gA, gB, tid);
            cp_arrive(mb + 16u * wbuf);
        }

        // phase bookkeeping for NSTAGE=4 (derived from fill/consume sequences)
        if ((it & 3) == 3) fp ^= 1u;
        if ((it & 3) == 0) ep ^= 1u;
        rbuf++; if (rbuf == NSTAGE) rbuf = 0;
        wbuf++; if (wbuf == NSTAGE) wbuf = 0;
    }

    // epilogue: direct fp32 stores (float2, 32B-sector aligned per lane quad)
    float* yBase = Y + (size_t)(mt * 128 + wm * 64) * D_OUT + nt * 256 + wn * 64;
    const int qr = lane >> 2;
    const int qc = (lane & 3) * 2;
#pragma unroll
    for (int mi = 0; mi < 4; mi++) {
        float* y0 = yBase + (size_t)(mi * 16 + qr) * D_OUT + qc;
        float* y1 = y0 + (size_t)8 * D_OUT;
#pragma unroll
        for (int nj = 0; nj < 8; nj++) {
            *reinterpret_cast<float2*>(y0 + nj * 8) = make_float2(acc[mi][nj][0], acc[mi][nj][1]);
            *reinterpret_cast<float2*>(y1 + nj * 8) = make_float2(acc[mi][nj][2], acc[mi][nj][3]);
        }
    }
}

// ============================================================================
extern "C" void kernel_launch(void* const* d_in, const int* in_sizes, int n_in,
                              void* d_out, int out_size) {
    (void)in_sizes; (void)n_in; (void)out_size;
    const float* X  = (const float*)d_in[0];
    const float* Wn = (const float*)d_in[1];
    const float* c1 = (const float*)d_in[2];
    const float* ck = (const float*)d_in[3];
    const float* L1 = (const float*)d_in[4];
    const float* L2 = (const float*)d_in[5];
    float* Y = (float*)d_out;

    prep_x_kernel<<<16384, 256>>>(X);
    prep_w_kernel<<<dim3(128, 64), 256>>>(Wn, c1, ck, L1, L2);
    cudaFuncSetAttribute(qlora_gemm, cudaFuncAttributeMaxDynamicSharedMemorySize, SMEM_DYN);
    qlora_gemm<<<dim3(N_TILES, M_TILES), 256, SMEM_DYN>>>(Y);
}